// round 3
// baseline (speedup 1.0000x reference)
#include <cuda_runtime.h>
#include <math_constants.h>
#include <cstdint>

// Problem constants (fixed by the dataset)
#define NTOK 16384          // 8*2048 tokens
#define DIM  256            // embedding dim
#define KC   8192           // codebook size
#define DECAYF 0.99f
#define OMDF   0.01f
#define EPSF   1e-5f
#define CWF    0.25f

// GEMM tiling
#define BM  128
#define BN  128
#define BK  16
#define BMP 132
#define BNP 132

// ---------------- scratch (device globals; no allocations allowed) -------
__device__ float g_cluster[KC];
__device__ float g_embed_sum[KC * DIM];
__device__ float g_esq[KC];
__device__ int   g_indices[NTOK];
__device__ int   g_cand1[NTOK];
__device__ int   g_cand2[NTOK];
__device__ float g_loss;

// ---------------- init: zero scratch -------------------------------------
__global__ void init_kernel() {
    int i = blockIdx.x * blockDim.x + threadIdx.x;
    if (i < KC * DIM) g_embed_sum[i] = 0.0f;
    if (i < KC)       g_cluster[i] = 0.0f;
    if (i == 0)       g_loss = 0.0f;
}

// ---------------- e_sq[k] = ||E_k||^2 (one warp per code) ----------------
__global__ void esq_kernel(const float* __restrict__ emb) {
    int gw   = (blockIdx.x * blockDim.x + threadIdx.x) >> 5;
    int lane = threadIdx.x & 31;
    if (gw >= KC) return;
    const float4* e4 = reinterpret_cast<const float4*>(emb + (size_t)gw * DIM);
    float4 a = e4[lane * 2];
    float4 b = e4[lane * 2 + 1];
    float s = a.x*a.x + a.y*a.y + a.z*a.z + a.w*a.w
            + b.x*b.x + b.y*b.y + b.z*b.z + b.w*b.w;
    #pragma unroll
    for (int o = 16; o; o >>= 1) s += __shfl_xor_sync(0xffffffffu, s, o);
    if (lane == 0) g_esq[gw] = s;
}

// ---------------- fused distance + top-2 argmin GEMM ---------------------
__device__ __forceinline__ unsigned int ford(float f) {
    unsigned int u = __float_as_uint(f);
    return (u & 0x80000000u) ? ~u : (u | 0x80000000u);
}
__device__ __forceinline__ unsigned long long packkey(float v, int idx) {
    return ((unsigned long long)ford(v) << 32) | (unsigned int)idx;
}

__global__ __launch_bounds__(256, 1)
void argmin_kernel(const float* __restrict__ z, const float* __restrict__ emb) {
    extern __shared__ float sm[];
    float* zs  = sm;                              // [DIM][BMP] transposed z tile
    float* esA = sm + DIM * BMP;                  // [2][BK][BNP] double-buffered E
    unsigned long long* red1 =
        reinterpret_cast<unsigned long long*>(sm + DIM * BMP + 2 * BK * BNP); // [BM]
    unsigned long long* red2 = red1 + BM;                                     // [BM]

    const int tid = threadIdx.x;
    const int tx  = tid & 15;     // column group (8 codes)
    const int ty  = tid >> 4;     // row group (8 tokens)
    const int m0  = blockIdx.x * BM;

    if (tid < BM) { red1[tid] = 0xFFFFFFFFFFFFFFFFULL; red2[tid] = 0xFFFFFFFFFFFFFFFFULL; }

    // Load z tile transposed: zs[k][m]
    for (int i = tid; i < BM * (DIM / 4); i += 256) {
        int m  = i >> 6;
        int kq = (i & 63) << 2;
        float4 v = *reinterpret_cast<const float4*>(z + (size_t)(m0 + m) * DIM + kq);
        zs[(kq + 0) * BMP + m] = v.x;
        zs[(kq + 1) * BMP + m] = v.y;
        zs[(kq + 2) * BMP + m] = v.z;
        zs[(kq + 3) * BMP + m] = v.w;
    }

    float m1[8], m2v[8];
    int   i1[8], i2[8];
    #pragma unroll
    for (int i = 0; i < 8; i++) {
        m1[i] = CUDART_INF_F; m2v[i] = CUDART_INF_F; i1[i] = 0; i2[i] = 0;
    }

    __syncthreads();

    for (int n0 = 0; n0 < KC; n0 += BN) {
        unsigned long long acc[8][4];
        #pragma unroll
        for (int i = 0; i < 8; i++)
            #pragma unroll
            for (int j = 0; j < 4; j++) acc[i][j] = 0ULL;

        // stage first E sub-tile into buffer 0
        #pragma unroll
        for (int t = 0; t < 2; t++) {
            int j  = tid * 2 + t;
            int n  = j >> 2;
            int kq = (j & 3) << 2;
            float4 v = *reinterpret_cast<const float4*>(emb + (size_t)(n0 + n) * DIM + kq);
            esA[(kq + 0) * BNP + n] = v.x;
            esA[(kq + 1) * BNP + n] = v.y;
            esA[(kq + 2) * BNP + n] = v.z;
            esA[(kq + 3) * BNP + n] = v.w;
        }
        __syncthreads();

        #pragma unroll 1
        for (int kk = 0; kk < DIM; kk += BK) {
            const int buf = (kk >> 4) & 1;
            const float* es = esA + buf * (BK * BNP);
            const bool has_next = (kk + BK) < DIM;

            float4 pre[2];
            int pn[2], pk[2];
            if (has_next) {
                #pragma unroll
                for (int t = 0; t < 2; t++) {
                    int j = tid * 2 + t;
                    pn[t] = j >> 2;
                    pk[t] = (j & 3) << 2;
                    pre[t] = *reinterpret_cast<const float4*>(
                        emb + (size_t)(n0 + pn[t]) * DIM + kk + BK + pk[t]);
                }
            }

            #pragma unroll
            for (int k = 0; k < BK; k++) {
                float4 alo = *reinterpret_cast<const float4*>(&zs[(kk + k) * BMP + ty * 8]);
                float4 ahi = *reinterpret_cast<const float4*>(&zs[(kk + k) * BMP + ty * 8 + 4]);
                unsigned long long b2[4];
                #pragma unroll
                for (int j = 0; j < 4; j++)
                    b2[j] = *reinterpret_cast<const unsigned long long*>(
                        &es[k * BNP + tx * 8 + j * 2]);
                float a_s[8] = {alo.x, alo.y, alo.z, alo.w, ahi.x, ahi.y, ahi.z, ahi.w};
                #pragma unroll
                for (int i = 0; i < 8; i++) {
                    unsigned long long a2;
                    asm("mov.b64 %0, {%1, %1};" : "=l"(a2) : "f"(a_s[i]));
                    #pragma unroll
                    for (int j = 0; j < 4; j++)
                        asm("fma.rn.f32x2 %0, %1, %2, %0;"
                            : "+l"(acc[i][j]) : "l"(a2), "l"(b2[j]));
                }
            }

            if (has_next) {
                float* dst = esA + (buf ^ 1) * (BK * BNP);
                #pragma unroll
                for (int t = 0; t < 2; t++) {
                    dst[(pk[t] + 0) * BNP + pn[t]] = pre[t].x;
                    dst[(pk[t] + 1) * BNP + pn[t]] = pre[t].y;
                    dst[(pk[t] + 2) * BNP + pn[t]] = pre[t].z;
                    dst[(pk[t] + 3) * BNP + pn[t]] = pre[t].w;
                }
            }
            __syncthreads();
        }

        // chunk epilogue: scores -> running top-2 per row (registers only)
        const int nbase = n0 + tx * 8;
        #pragma unroll
        for (int j2 = 0; j2 < 4; j2++) {
            float eq0 = g_esq[nbase + j2 * 2];
            float eq1 = g_esq[nbase + j2 * 2 + 1];
            #pragma unroll
            for (int i = 0; i < 8; i++) {
                float2 p = *reinterpret_cast<float2*>(&acc[i][j2]);
                float d0 = eq0 - 2.0f * p.x;  int k0 = nbase + j2 * 2;
                float d1 = eq1 - 2.0f * p.y;  int k1 = k0 + 1;
                if (d0 < m2v[i]) {
                    if (d0 < m1[i]) { m2v[i] = m1[i]; i2[i] = i1[i]; m1[i] = d0; i1[i] = k0; }
                    else            { m2v[i] = d0; i2[i] = k0; }
                }
                if (d1 < m2v[i]) {
                    if (d1 < m1[i]) { m2v[i] = m1[i]; i2[i] = i1[i]; m1[i] = d1; i1[i] = k1; }
                    else            { m2v[i] = d1; i2[i] = k1; }
                }
            }
        }
    }

    // cross-thread reduce: global top-2 per row
    #pragma unroll
    for (int i = 0; i < 8; i++)
        atomicMin(&red1[ty * 8 + i], packkey(m1[i], i1[i]));
    __syncthreads();
    #pragma unroll
    for (int i = 0; i < 8; i++) {
        int widx = (int)(red1[ty * 8 + i] & 0xFFFFFFFFu);
        unsigned long long cand = (i1[i] == widx) ? packkey(m2v[i], i2[i])
                                                  : packkey(m1[i], i1[i]);
        atomicMin(&red2[ty * 8 + i], cand);
    }
    __syncthreads();
    if (tid < BM) {
        g_cand1[m0 + tid] = (int)(red1[tid] & 0xFFFFFFFFu);
        g_cand2[m0 + tid] = (int)(red2[tid] & 0xFFFFFFFFu);
    }
}

// ---------------- rescore: replicate reference fp32 rounding -------------
// ref: d = fl( fl(z_sq + e_sq) - fl(2*ze) ), z_sq = sequential scalar fp32 sum
__global__ void rescore_kernel(const float* __restrict__ z,
                               const float* __restrict__ emb) {
    int n = blockIdx.x * blockDim.x + threadIdx.x;
    if (n >= NTOK) return;
    const float* zr = z + (size_t)n * DIM;

    // z_sq: strict sequential fp32 (mul then add, round each op)
    float S = 0.0f;
    #pragma unroll 8
    for (int i = 0; i < DIM; i++)
        S = __fadd_rn(S, __fmul_rn(zr[i], zr[i]));

    int ia = g_cand1[n];
    int ib = g_cand2[n];
    const float* ea = emb + (size_t)ia * DIM;
    const float* eb = emb + (size_t)ib * DIM;

    // near-exact dots in double (4 accumulators)
    double a0 = 0, a1 = 0, a2 = 0, a3 = 0;
    double b0 = 0, b1 = 0, b2 = 0, b3 = 0;
    #pragma unroll 4
    for (int i = 0; i < DIM; i += 4) {
        a0 += (double)zr[i + 0] * (double)ea[i + 0];
        a1 += (double)zr[i + 1] * (double)ea[i + 1];
        a2 += (double)zr[i + 2] * (double)ea[i + 2];
        a3 += (double)zr[i + 3] * (double)ea[i + 3];
        b0 += (double)zr[i + 0] * (double)eb[i + 0];
        b1 += (double)zr[i + 1] * (double)eb[i + 1];
        b2 += (double)zr[i + 2] * (double)eb[i + 2];
        b3 += (double)zr[i + 3] * (double)eb[i + 3];
    }
    float zea = (float)((a0 + a1) + (a2 + a3));
    float zeb = (float)((b0 + b1) + (b2 + b3));

    float qa = __fsub_rn(__fadd_rn(S, g_esq[ia]), __fmul_rn(2.0f, zea));
    float qb = __fsub_rn(__fadd_rn(S, g_esq[ib]), __fmul_rn(2.0f, zeb));

    int pick;
    if (qa < qb)      pick = ia;
    else if (qb < qa) pick = ib;
    else              pick = (ia < ib) ? ia : ib;   // quantized tie: first index
    g_indices[n] = pick;
}

// ---------------- per-token epilogue: gather/ST/loss/segment sums --------
__global__ void epilogue_kernel(const float* __restrict__ z,
                                const float* __restrict__ emb,
                                float* __restrict__ out_zq,
                                float* __restrict__ out_idx) {
    int gw   = (blockIdx.x * blockDim.x + threadIdx.x) >> 5;
    int lane = threadIdx.x & 31;
    if (gw >= NTOK) return;
    int idx = g_indices[gw];
    const float4* zr = reinterpret_cast<const float4*>(z   + (size_t)gw  * DIM);
    const float4* er = reinterpret_cast<const float4*>(emb + (size_t)idx * DIM);
    float4* o = reinterpret_cast<float4*>(out_zq + (size_t)gw * DIM);
    float* esum = g_embed_sum + (size_t)idx * DIM;
    float loss = 0.0f;
    #pragma unroll
    for (int j = lane; j < DIM / 4; j += 32) {
        float4 zv = zr[j], ev = er[j];
        float dx = ev.x - zv.x, dy = ev.y - zv.y, dz = ev.z - zv.z, dw = ev.w - zv.w;
        float4 q;
        q.x = zv.x + dx; q.y = zv.y + dy; q.z = zv.z + dz; q.w = zv.w + dw;
        o[j] = q;
        loss += dx * dx + dy * dy + dz * dz + dw * dw;
        atomicAdd(&esum[j * 4 + 0], zv.x);
        atomicAdd(&esum[j * 4 + 1], zv.y);
        atomicAdd(&esum[j * 4 + 2], zv.z);
        atomicAdd(&esum[j * 4 + 3], zv.w);
    }
    #pragma unroll
    for (int off = 16; off; off >>= 1) loss += __shfl_xor_sync(0xffffffffu, loss, off);
    if (lane == 0) {
        atomicAdd(&g_loss, loss);
        atomicAdd(&g_cluster[idx], 1.0f);
        out_idx[gw] = (float)idx;
    }
}

// ---------------- EMA finalize + output writes ---------------------------
__global__ void finalize_kernel(const float* __restrict__ ema_cs,
                                const float* __restrict__ ema_es,
                                float* __restrict__ out_emb,
                                float* __restrict__ out_ecs,
                                float* __restrict__ out_ees,
                                float* __restrict__ out_l1,
                                float* __restrict__ out_l2) {
    int i = blockIdx.x * blockDim.x + threadIdx.x;
    if (i < KC * DIM) {
        int k = i >> 8;
        float ncs = DECAYF * ema_cs[k] + OMDF * g_cluster[k];
        float nes = DECAYF * ema_es[i] + OMDF * g_embed_sum[i];
        out_ees[i] = nes;
        out_emb[i] = nes / (ncs + EPSF);
    }
    if (i < KC) {
        out_ecs[i] = DECAYF * ema_cs[i] + OMDF * g_cluster[i];
    }
    if (i == 0) {
        float L = CWF * (g_loss / (float)(NTOK * DIM));
        out_l1[0] = L;
        out_l2[0] = L;
    }
}

// ---------------- launch ---------------------------------------------------
extern "C" void kernel_launch(void* const* d_in, const int* in_sizes, int n_in,
                              void* d_out, int out_size) {
    const float* z      = (const float*)d_in[0];
    const float* emb    = (const float*)d_in[1];
    const float* ema_cs = (const float*)d_in[2];
    const float* ema_es = (const float*)d_in[3];
    float* out = (float*)d_out;

    float* out_zq  = out;
    float* out_idx = out_zq + (size_t)NTOK * DIM;
    float* out_l1  = out_idx + NTOK;
    float* out_l2  = out_l1 + 1;
    float* out_emb = out_l2 + 1;
    float* out_ecs = out_emb + (size_t)KC * DIM;
    float* out_ees = out_ecs + KC;

    size_t smem = (size_t)(DIM * BMP + 2 * BK * BNP) * sizeof(float)
                + (size_t)(2 * BM) * sizeof(unsigned long long);
    cudaFuncSetAttribute(argmin_kernel,
                         cudaFuncAttributeMaxDynamicSharedMemorySize, (int)smem);

    init_kernel<<<(KC * DIM + 255) / 256, 256>>>();
    esq_kernel<<<(KC * 32 + 255) / 256, 256>>>(emb);
    argmin_kernel<<<NTOK / BM, 256, smem>>>(z, emb);
    rescore_kernel<<<(NTOK + 255) / 256, 256>>>(z, emb);
    epilogue_kernel<<<(NTOK * 32 + 255) / 256, 256>>>(z, emb, out_zq, out_idx);
    finalize_kernel<<<(KC * DIM + 255) / 256, 256>>>(ema_cs, ema_es, out_emb,
                                                     out_ecs, out_ees, out_l1, out_l2);
}

// round 6
// speedup vs baseline: 2.3118x; 2.3118x over previous
#include <cuda_runtime.h>
#include <math_constants.h>
#include <cstdint>

// Problem constants
#define NTOK 16384
#define DIM  256
#define KC   8192
#define DECAYF 0.99f
#define OMDF   0.01f
#define EPSF   1e-5f
#define CWF    0.25f

// GEMM tiling
#define BM 128
#define BN 128
#define PITCH 68                  // E smem row pitch (floats) -> conflict-free B LDS
#define EBUF (128 * PITCH)        // floats per E buffer (8704)
#define AFRAG (8 * 32 * 32 * 4)   // A fragment layout floats (32768 = 128KB)
#define ZPITCH 132                // z staging pitch

// ---------------- scratch ------------------------------------------------
__device__ float g_cluster[KC];
__device__ float g_embed_sum[KC * DIM];
__device__ float g_esq[KC];
__device__ float g_esqh[KC];      // -0.5 * esq
__device__ int   g_indices[NTOK];
__device__ int   g_cand[4 * NTOK];
__device__ float g_loss;

// ---------------- helpers -------------------------------------------------
__device__ __forceinline__ unsigned tf32_bits(float x) {
    unsigned r;
    asm("cvt.rna.tf32.f32 %0, %1;" : "=r"(r) : "f"(x));
    return r;
}
__device__ __forceinline__ unsigned int ford(float f) {
    unsigned int u = __float_as_uint(f);
    return (u & 0x80000000u) ? ~u : (u | 0x80000000u);  // order-preserving
}
__device__ __forceinline__ void mma_tf32(float* c, const unsigned* a, const unsigned* b) {
    asm volatile(
        "mma.sync.aligned.m16n8k8.row.col.f32.tf32.tf32.f32 "
        "{%0,%1,%2,%3}, {%4,%5,%6,%7}, {%8,%9}, {%0,%1,%2,%3};"
        : "+f"(c[0]), "+f"(c[1]), "+f"(c[2]), "+f"(c[3])
        : "r"(a[0]), "r"(a[1]), "r"(a[2]), "r"(a[3]), "r"(b[0]), "r"(b[1]));
}
#define INSERT4(T, key) do { \
    if ((key) > (T)[3]) { \
        if ((key) > (T)[0])      { (T)[3]=(T)[2]; (T)[2]=(T)[1]; (T)[1]=(T)[0]; (T)[0]=(key); } \
        else if ((key) > (T)[1]) { (T)[3]=(T)[2]; (T)[2]=(T)[1]; (T)[1]=(key); } \
        else if ((key) > (T)[2]) { (T)[3]=(T)[2]; (T)[2]=(key); } \
        else                     { (T)[3]=(key); } \
    } } while (0)

// ---------------- init ----------------------------------------------------
__global__ void init_kernel() {
    int i = blockIdx.x * blockDim.x + threadIdx.x;
    if (i < KC * DIM) g_embed_sum[i] = 0.0f;
    if (i < KC)       g_cluster[i] = 0.0f;
    if (i == 0)       g_loss = 0.0f;
}

// ---------------- e_sq (frozen numerics) + (-e_sq/2) ----------------------
__global__ void esq_kernel(const float* __restrict__ emb) {
    int gw   = (blockIdx.x * blockDim.x + threadIdx.x) >> 5;
    int lane = threadIdx.x & 31;
    if (gw >= KC) return;
    const float4* e4 = reinterpret_cast<const float4*>(emb + (size_t)gw * DIM);
    float4 a = e4[lane * 2];
    float4 b = e4[lane * 2 + 1];
    float s = a.x*a.x + a.y*a.y + a.z*a.z + a.w*a.w
            + b.x*b.x + b.y*b.y + b.z*b.z + b.w*b.w;
    #pragma unroll
    for (int o = 16; o; o >>= 1) s += __shfl_xor_sync(0xffffffffu, s, o);
    if (lane == 0) { g_esq[gw] = s; g_esqh[gw] = -0.5f * s; }
}

// ---------------- mma.sync tf32 argmin (top-4 candidates) -----------------
// D = (-esq/2) + z.e ; argmax D == argmin distance. 8 warps = 2(M) x 4(N).
__global__ __launch_bounds__(256, 1)
void argmin_kernel(const float* __restrict__ z, const float* __restrict__ emb) {
    extern __shared__ float sm[];
    float* afr = sm;              // A fragments [mf 8][ks 32][lane 32][4]
    float* es  = sm + AFRAG;      // 2 x EBUF (E chunks); reused for staging/merge

    const int tid  = threadIdx.x;
    const int lane = tid & 31;
    const int warp = tid >> 5;
    const int wr   = warp >> 2;   // warp row (0..1) -> 64 token rows
    const int wn   = warp & 3;    // warp col (0..3) -> 32 codes
    const int m0   = blockIdx.x * BM;

    // ---- stage z into tf32 A-fragment layout (two 128-dim halves) ----
    for (int h = 0; h < 2; h++) {
        for (int i = tid; i < 128 * 32; i += 256) {
            int row = i >> 5, dq = i & 31;
            float4 v = __ldg(reinterpret_cast<const float4*>(
                z + (size_t)(m0 + row) * DIM + h * 128 + dq * 4));
            float* d = es + row * ZPITCH + dq * 4;
            d[0] = __uint_as_float(tf32_bits(v.x));
            d[1] = __uint_as_float(tf32_bits(v.y));
            d[2] = __uint_as_float(tf32_bits(v.z));
            d[3] = __uint_as_float(tf32_bits(v.w));
        }
        __syncthreads();
        for (int s = tid; s < 4096; s += 256) {
            int ls = s & 31, ksl = (s >> 5) & 15, mf = s >> 9;
            int r = ls >> 2, cc = ls & 3;
            const float* zb  = es + (mf * 16 + r) * ZPITCH;
            const float* zb8 = zb + 8 * ZPITCH;
            int d0 = ksl * 8 + cc;
            float4 w = make_float4(zb[d0], zb8[d0], zb[d0 + 4], zb8[d0 + 4]);
            *reinterpret_cast<float4*>(
                afr + ((mf * 32 + h * 16 + ksl) * 32 + ls) * 4) = w;
        }
        __syncthreads();
    }

    unsigned long long top[8][4];
    #pragma unroll
    for (int i = 0; i < 8; i++)
        #pragma unroll
        for (int j = 0; j < 4; j++) top[i][j] = 0ULL;

    #pragma unroll 1
    for (int nt = 0; nt < KC / BN; nt++) {
        // init accumulators with -esq/2 (column-dependent)
        float acc[4][4][4];
        #pragma unroll
        for (int nfl = 0; nfl < 4; nfl++) {
            int j0 = nt * BN + wn * 32 + nfl * 8 + (lane & 3) * 2;
            float v0 = __ldg(&g_esqh[j0]), v1 = __ldg(&g_esqh[j0 + 1]);
            #pragma unroll
            for (int mfl = 0; mfl < 4; mfl++) {
                acc[mfl][nfl][0] = v0; acc[mfl][nfl][1] = v1;
                acc[mfl][nfl][2] = v0; acc[mfl][nfl][3] = v1;
            }
        }

        // stage k-chunk 0 (64 dims) into buffer 0
        #pragma unroll
        for (int it = 0; it < 8; it++) {
            int idx = tid + it * 256;
            int code = idx >> 4, dq = idx & 15;
            float4 v = __ldg(reinterpret_cast<const float4*>(
                emb + (size_t)(nt * BN + code) * DIM + dq * 4));
            float* d = es + code * PITCH + dq * 4;
            d[0] = __uint_as_float(tf32_bits(v.x));
            d[1] = __uint_as_float(tf32_bits(v.y));
            d[2] = __uint_as_float(tf32_bits(v.z));
            d[3] = __uint_as_float(tf32_bits(v.w));
        }
        __syncthreads();

        #pragma unroll 1
        for (int c = 0; c < 4; c++) {
            const int buf = c & 1;
            float4 pre[8];
            if (c < 3) {
                #pragma unroll
                for (int it = 0; it < 8; it++) {
                    int idx = tid + it * 256;
                    int code = idx >> 4, dq = idx & 15;
                    pre[it] = __ldg(reinterpret_cast<const float4*>(
                        emb + (size_t)(nt * BN + code) * DIM + (c + 1) * 64 + dq * 4));
                }
            }
            const float* eb = es + buf * EBUF;
            #pragma unroll
            for (int ks = 0; ks < 8; ks++) {
                int ksg = c * 8 + ks;
                unsigned a[4][4], b[4][2];
                #pragma unroll
                for (int mfl = 0; mfl < 4; mfl++) {
                    float4 av = *reinterpret_cast<const float4*>(
                        afr + (((wr * 4 + mfl) * 32 + ksg) * 32 + lane) * 4);
                    a[mfl][0] = __float_as_uint(av.x);
                    a[mfl][1] = __float_as_uint(av.y);
                    a[mfl][2] = __float_as_uint(av.z);
                    a[mfl][3] = __float_as_uint(av.w);
                }
                #pragma unroll
                for (int nfl = 0; nfl < 4; nfl++) {
                    const float* p = eb + (wn * 32 + nfl * 8 + (lane >> 2)) * PITCH
                                        + ks * 8 + (lane & 3);
                    b[nfl][0] = __float_as_uint(p[0]);
                    b[nfl][1] = __float_as_uint(p[4]);
                }
                #pragma unroll
                for (int mfl = 0; mfl < 4; mfl++)
                    #pragma unroll
                    for (int nfl = 0; nfl < 4; nfl++)
                        mma_tf32(acc[mfl][nfl], a[mfl], b[nfl]);
            }
            if (c < 3) {
                float* d0 = es + (buf ^ 1) * EBUF;
                #pragma unroll
                for (int it = 0; it < 8; it++) {
                    int idx = tid + it * 256;
                    int code = idx >> 4, dq = idx & 15;
                    float* d = d0 + code * PITCH + dq * 4;
                    d[0] = __uint_as_float(tf32_bits(pre[it].x));
                    d[1] = __uint_as_float(tf32_bits(pre[it].y));
                    d[2] = __uint_as_float(tf32_bits(pre[it].z));
                    d[3] = __uint_as_float(tf32_bits(pre[it].w));
                }
            }
            __syncthreads();
        }

        // per-tile epilogue: insert 64 scores into per-thread top-4
        #pragma unroll
        for (int mfl = 0; mfl < 4; mfl++)
            #pragma unroll
            for (int nfl = 0; nfl < 4; nfl++)
                #pragma unroll
                for (int j = 0; j < 4; j++) {
                    float v = acc[mfl][nfl][j];
                    int col = nt * BN + wn * 32 + nfl * 8 + (lane & 3) * 2 + (j & 1);
                    int rs  = mfl * 2 + (j >> 1);
                    unsigned long long key =
                        ((unsigned long long)ford(v) << 32) | (unsigned)col;
                    INSERT4(top[rs], key);
                }
    }

    // ---- cross-thread merge: red[(owner*4+j)*128 + row] ----
    __syncthreads();
    unsigned long long* red = reinterpret_cast<unsigned long long*>(es);
    const int owner = wn * 4 + (lane & 3);
    #pragma unroll
    for (int rs = 0; rs < 8; rs++) {
        int row = wr * 64 + (rs >> 1) * 16 + (rs & 1) * 8 + (lane >> 2);
        #pragma unroll
        for (int j = 0; j < 4; j++)
            red[(owner * 4 + j) * 128 + row] = top[rs][j];
    }
    __syncthreads();
    if (tid < 128) {
        unsigned long long t[4] = {0ULL, 0ULL, 0ULL, 0ULL};
        for (int i = 0; i < 64; i++) {
            unsigned long long k = red[i * 128 + tid];
            INSERT4(t, k);
        }
        int row = m0 + tid;
        g_cand[0 * NTOK + row] = (int)(t[0] & 0xffffffffu);
        g_cand[1 * NTOK + row] = (int)(t[1] & 0xffffffffu);
        g_cand[2 * NTOK + row] = (int)(t[2] & 0xffffffffu);
        g_cand[3 * NTOK + row] = (int)(t[3] & 0xffffffffu);
    }
}

// ---------------- rescore: warp per token, exact reference rounding -------
__global__ __launch_bounds__(256)
void rescore_kernel(const float* __restrict__ z, const float* __restrict__ emb) {
    const int w    = (blockIdx.x * blockDim.x + threadIdx.x) >> 5;
    const int lane = threadIdx.x & 31;
    if (w >= NTOK) return;
    const float* zr = z + (size_t)w * DIM;

    float zv[8];
    #pragma unroll
    for (int j = 0; j < 8; j++) zv[j] = __ldg(&zr[j * 32 + lane]);

    // z_sq: strict sequential fp32 in index order (frozen — matches reference)
    float S = 0.0f;
    #pragma unroll
    for (int j = 0; j < 8; j++)
        for (int ii = 0; ii < 32; ii++) {
            float v = __shfl_sync(0xffffffffu, zv[j], ii);
            S = __fadd_rn(S, __fmul_rn(v, v));
        }

    float bq = 0.0f; int bi = -1;
    #pragma unroll
    for (int c = 0; c < 4; c++) {
        int idx = g_cand[c * NTOK + w];
        const float* e = emb + (size_t)idx * DIM;
        double acc = 0.0;
        #pragma unroll
        for (int j = 0; j < 8; j++)
            acc += (double)zv[j] * (double)__ldg(&e[j * 32 + lane]);
        #pragma unroll
        for (int o = 16; o; o >>= 1)
            acc += __shfl_down_sync(0xffffffffu, acc, o);
        acc = __shfl_sync(0xffffffffu, acc, 0);
        float q = __fsub_rn(__fadd_rn(S, __ldg(&g_esq[idx])),
                            __fmul_rn(2.0f, (float)acc));
        if (bi < 0 || q < bq || (q == bq && idx < bi)) { bq = q; bi = idx; }
    }
    if (lane == 0) g_indices[w] = bi;
}

// ---------------- per-token epilogue --------------------------------------
__global__ void epilogue_kernel(const float* __restrict__ z,
                                const float* __restrict__ emb,
                                float* __restrict__ out_zq,
                                float* __restrict__ out_idx) {
    int gw   = (blockIdx.x * blockDim.x + threadIdx.x) >> 5;
    int lane = threadIdx.x & 31;
    if (gw >= NTOK) return;
    int idx = g_indices[gw];
    const float4* zr = reinterpret_cast<const float4*>(z   + (size_t)gw  * DIM);
    const float4* er = reinterpret_cast<const float4*>(emb + (size_t)idx * DIM);
    float4* o = reinterpret_cast<float4*>(out_zq + (size_t)gw * DIM);
    float* esum = g_embed_sum + (size_t)idx * DIM;
    float loss = 0.0f;
    #pragma unroll
    for (int j = lane; j < DIM / 4; j += 32) {
        float4 zv = zr[j], ev = er[j];
        float dx = ev.x - zv.x, dy = ev.y - zv.y, dz = ev.z - zv.z, dw = ev.w - zv.w;
        float4 q;
        q.x = zv.x + dx; q.y = zv.y + dy; q.z = zv.z + dz; q.w = zv.w + dw;
        o[j] = q;
        loss += dx * dx + dy * dy + dz * dz + dw * dw;
        atomicAdd(&esum[j * 4 + 0], zv.x);
        atomicAdd(&esum[j * 4 + 1], zv.y);
        atomicAdd(&esum[j * 4 + 2], zv.z);
        atomicAdd(&esum[j * 4 + 3], zv.w);
    }
    #pragma unroll
    for (int off = 16; off; off >>= 1) loss += __shfl_xor_sync(0xffffffffu, loss, off);
    if (lane == 0) {
        atomicAdd(&g_loss, loss);
        atomicAdd(&g_cluster[idx], 1.0f);
        out_idx[gw] = (float)idx;
    }
}

// ---------------- EMA finalize --------------------------------------------
__global__ void finalize_kernel(const float* __restrict__ ema_cs,
                                const float* __restrict__ ema_es,
                                float* __restrict__ out_emb,
                                float* __restrict__ out_ecs,
                                float* __restrict__ out_ees,
                                float* __restrict__ out_l1,
                                float* __restrict__ out_l2) {
    int i = blockIdx.x * blockDim.x + threadIdx.x;
    if (i < KC * DIM) {
        int k = i >> 8;
        float ncs = DECAYF * ema_cs[k] + OMDF * g_cluster[k];
        float nes = DECAYF * ema_es[i] + OMDF * g_embed_sum[i];
        out_ees[i] = nes;
        out_emb[i] = nes / (ncs + EPSF);
    }
    if (i < KC) {
        out_ecs[i] = DECAYF * ema_cs[i] + OMDF * g_cluster[i];
    }
    if (i == 0) {
        float L = CWF * (g_loss / (float)(NTOK * DIM));
        out_l1[0] = L;
        out_l2[0] = L;
    }
}

// ---------------- launch ---------------------------------------------------
extern "C" void kernel_launch(void* const* d_in, const int* in_sizes, int n_in,
                              void* d_out, int out_size) {
    const float* z      = (const float*)d_in[0];
    const float* emb    = (const float*)d_in[1];
    const float* ema_cs = (const float*)d_in[2];
    const float* ema_es = (const float*)d_in[3];
    float* out = (float*)d_out;

    float* out_zq  = out;
    float* out_idx = out_zq + (size_t)NTOK * DIM;
    float* out_l1  = out_idx + NTOK;
    float* out_l2  = out_l1 + 1;
    float* out_emb = out_l2 + 1;
    float* out_ecs = out_emb + (size_t)KC * DIM;
    float* out_ees = out_ecs + KC;

    const int smem = (AFRAG + 2 * EBUF) * 4;   // 200704 bytes
    cudaFuncSetAttribute(argmin_kernel,
                         cudaFuncAttributeMaxDynamicSharedMemorySize, smem);

    init_kernel<<<(KC * DIM + 255) / 256, 256>>>();
    esq_kernel<<<(KC * 32 + 255) / 256, 256>>>(emb);
    argmin_kernel<<<NTOK / BM, 256, smem>>>(z, emb);
    rescore_kernel<<<(NTOK * 32) / 256, 256>>>(z, emb);
    epilogue_kernel<<<(NTOK * 32 + 255) / 256, 256>>>(z, emb, out_zq, out_idx);
    finalize_kernel<<<(KC * DIM + 255) / 256, 256>>>(ema_cs, ema_es, out_emb,
                                                     out_ecs, out_ees, out_l1, out_l2);
}